// round 4
// baseline (speedup 1.0000x reference)
#include <cuda_runtime.h>
#include <cstdint>
#include <float.h>

// Sparsemax, one WARP per row — zero block barriers, all shfl.
//
// Exact algorithm: tau >= rowmax - 1, so support ⊂ C = { x > rowmax - 1 }
// (|C| ~ 5 for Gaussian rows). During the single streaming pass each lane
// keeps its top-4 values in registers; C is contained in those registers
// unless some lane's 4th-best exceeds the threshold (detected exactly by
// ballot; rare fallback re-scans the row from L2 with Michelot iteration).
// Newton/Michelot on the register candidates converges in ~3 iterations to
// the exact tau. The store pass re-reads the row from L2 (32 KB, resident).

#define THREADS 256
#define NWARP   8
#define COLS    8192
#define C4      (COLS / 4)          // 2048 float4 per row
#define GRID    296                 // 2 CTAs/SM -> 2368 rows in flight (74 MB in L2)

__global__ __launch_bounds__(THREADS, 4)    // caps regs at 64, we use ~52
void sparsemax_warp(const float* __restrict__ x, float* __restrict__ out, int rows)
{
    const int lane = threadIdx.x & 31;
    const int wid  = threadIdx.x >> 5;
    const long long wstride = (long long)gridDim.x * NWARP;

#pragma unroll 1
    for (long long r = (long long)blockIdx.x * NWARP + wid; r < rows; r += wstride) {
        const float4* __restrict__ xr = reinterpret_cast<const float4*>(x + r * COLS);

        // ---- pass 1: stream row once, keep per-lane top-4 in registers ----
        float k0 = -FLT_MAX, k1 = -FLT_MAX, k2 = -FLT_MAX, k3 = -FLT_MAX;
#define INS(v) do { float _v = (v);                                        \
        if (_v > k3) {                                                     \
            if (_v > k1) {                                                 \
                if (_v > k0) { k3 = k2; k2 = k1; k1 = k0; k0 = _v; }       \
                else         { k3 = k2; k2 = k1; k1 = _v; }                \
            } else {                                                       \
                if (_v > k2) { k3 = k2; k2 = _v; }                         \
                else         { k3 = _v; }                                  \
            }                                                              \
        } } while (0)

#pragma unroll 8
        for (int i = lane; i < C4; i += 32) {
            float4 v = xr[i];
            INS(v.x); INS(v.y); INS(v.z); INS(v.w);
        }
#undef INS

        // ---- warp max -> threshold ----
        float m = k0;
#pragma unroll
        for (int o = 16; o > 0; o >>= 1) m = fmaxf(m, __shfl_xor_sync(0xffffffffu, m, o));
        const float thresh = m - 1.0f;          // tau >= thresh always

        float tau;
        const unsigned ovf = __ballot_sync(0xffffffffu, k3 > thresh);
        if (ovf == 0u) {
            // ---- common path: all candidates live in k0..k3; Newton on regs ----
            float t0 = thresh;
#pragma unroll 1
            for (int it = 0; it < 64; ++it) {
                float s = 0.0f, k = 0.0f;
                if (k0 > t0) { s += k0; k += 1.0f; }
                if (k1 > t0) { s += k1; k += 1.0f; }
                if (k2 > t0) { s += k2; k += 1.0f; }
                if (k3 > t0) { s += k3; k += 1.0f; }
#pragma unroll
                for (int o = 16; o > 0; o >>= 1) {
                    s += __shfl_xor_sync(0xffffffffu, s, o);
                    k += __shfl_xor_sync(0xffffffffu, k, o);
                }
                if (k < 0.5f) break;             // safety (cannot happen in theory)
                float nt = (s - 1.0f) / k;
                if (nt == t0) break;             // exact fixed point
                t0 = nt;
            }
            tau = t0;
        } else {
            // ---- rare fallback: Michelot over the full row (L2-resident) ----
            float t0 = thresh;
#pragma unroll 1
            for (int it = 0; it < 64; ++it) {
                float s = 0.0f, k = 0.0f;
#pragma unroll 4
                for (int i = lane; i < C4; i += 32) {
                    float4 v = xr[i];
                    if (v.x > t0) { s += v.x; k += 1.0f; }
                    if (v.y > t0) { s += v.y; k += 1.0f; }
                    if (v.z > t0) { s += v.z; k += 1.0f; }
                    if (v.w > t0) { s += v.w; k += 1.0f; }
                }
#pragma unroll
                for (int o = 16; o > 0; o >>= 1) {
                    s += __shfl_xor_sync(0xffffffffu, s, o);
                    k += __shfl_xor_sync(0xffffffffu, k, o);
                }
                if (k < 0.5f) break;
                float nt = (s - 1.0f) / k;
                if (nt == t0) break;
                t0 = nt;
            }
            tau = t0;
        }

        // ---- pass 2: re-read row (L2 hit), emit max(x - tau, 0) ----
        float4* __restrict__ yr = reinterpret_cast<float4*>(out + r * COLS);
#pragma unroll 8
        for (int i = lane; i < C4; i += 32) {
            float4 v = xr[i];
            float4 o4;
            o4.x = fmaxf(v.x - tau, 0.0f);
            o4.y = fmaxf(v.y - tau, 0.0f);
            o4.z = fmaxf(v.z - tau, 0.0f);
            o4.w = fmaxf(v.w - tau, 0.0f);
            __stcs(yr + i, o4);
        }
    }
}

extern "C" void kernel_launch(void* const* d_in, const int* in_sizes, int n_in,
                              void* d_out, int out_size)
{
    const float* x = (const float*)d_in[0];
    float* out     = (float*)d_out;
    const int rows = in_sizes[0] / COLS;
    sparsemax_warp<<<GRID, THREADS>>>(x, out, rows);
}

// round 5
// speedup vs baseline: 1.2513x; 1.2513x over previous
#include <cuda_runtime.h>
#include <cstdint>
#include <float.h>

// Sparsemax, persistent CTAs. DRAM feeding decoupled from compute via
// cp.async.bulk.prefetch.L2 (row j+2), so the read stream never stalls on
// the CTA's serial phases. Row data is register-resident (single set).
//
// Exact algorithm: tau >= rowmax - 1 always, so the support is contained in
// C = { x > rowmax - 1 } (tiny for Gaussian rows). Gather C into smem from
// registers, solve exactly with Newton/Michelot (redundantly on every warp,
// no broadcast barrier), emit max(x - tau, 0) with streaming stores.

#define THREADS 512
#define COLS    8192
#define ROW_BYTES (COLS * 4)
#define CAP     512
#define GRID    296        // 2 CTAs/SM x 148 SMs
#define PFDIST  2          // prefetch distance in rows (per CTA)

// monotone float->uint encoding (order-preserving for atomicMax)
__device__ __forceinline__ unsigned encf(float f) {
    unsigned s = __float_as_uint(f);
    return (s & 0x80000000u) ? ~s : (s | 0x80000000u);
}
__device__ __forceinline__ float decf(unsigned u) {
    return __uint_as_float((u & 0x80000000u) ? (u & 0x7fffffffu) : ~u);
}
__device__ __forceinline__ void l2_prefetch_row(const void* p) {
    asm volatile("cp.async.bulk.prefetch.L2.global [%0], %1;"
                 :: "l"(p), "r"(ROW_BYTES) : "memory");
}

__global__ __launch_bounds__(THREADS, 2)
void sparsemax_l2pf(const float* __restrict__ x, float* __restrict__ out, int rows)
{
    __shared__ unsigned s_maxu[2];     // parity-slotted row-max accumulator
    __shared__ int      s_cnt[2];      // parity-slotted candidate count
    __shared__ float    s_cand[CAP];
    __shared__ float    s_red[32];     // fallback scratch
    __shared__ float    s_tau;         // fallback scratch
    __shared__ int      s_done;        // fallback scratch

    const int tid  = threadIdx.x;
    const int lane = tid & 31;

    if (tid == 0) { s_maxu[0] = 0u; s_maxu[1] = 0u; s_cnt[0] = 0; s_cnt[1] = 0; }

    const long long stride = gridDim.x;
    const long long j0 = blockIdx.x;

    // prologue: prefetch this CTA's first PFDIST rows into L2
    if (tid == 0) {
#pragma unroll
        for (int d = 0; d < PFDIST; ++d) {
            long long jp = j0 + (long long)d * stride;
            if (jp < rows) l2_prefetch_row(x + jp * COLS);
        }
    }
    __syncthreads();

    int p = 0;
#pragma unroll 1
    for (long long j = j0; j < rows; j += stride) {
        // ---- keep the DRAM->L2 stream fed (fire-and-forget) ----
        if (tid == 0) {
            long long jp = j + (long long)PFDIST * stride;
            if (jp < rows) l2_prefetch_row(x + jp * COLS);
        }

        // ---- load row j into registers (L2 hits thanks to prefetch) ----
        const float4* __restrict__ xr = reinterpret_cast<const float4*>(x + j * COLS);
        float4 v[4];
#pragma unroll
        for (int i = 0; i < 4; ++i) v[i] = __ldg(xr + tid + i * THREADS);

        // ---- row max: register chain + warp shfl + one shared atomicMax ----
        float m = -FLT_MAX;
#pragma unroll
        for (int i = 0; i < 4; ++i)
            m = fmaxf(m, fmaxf(fmaxf(v[i].x, v[i].y), fmaxf(v[i].z, v[i].w)));
#pragma unroll
        for (int o = 16; o > 0; o >>= 1) m = fmaxf(m, __shfl_xor_sync(0xffffffffu, m, o));
        if (lane == 0) atomicMax(&s_maxu[p], encf(m));
        __syncthreads();                                       // barrier 1
        if (tid == 0) { s_maxu[p ^ 1] = 0u; s_cnt[p ^ 1] = 0; }  // reset other slot
        const float thresh = decf(s_maxu[p]) - 1.0f;           // tau >= thresh

        // ---- gather candidates > thresh from registers (~6 hits/row) ----
#pragma unroll
        for (int i = 0; i < 4; ++i) {
            const float e[4] = {v[i].x, v[i].y, v[i].z, v[i].w};
#pragma unroll
            for (int k = 0; k < 4; ++k) {
                if (e[k] > thresh) {
                    int q = atomicAdd(&s_cnt[p], 1);
                    if (q < CAP) s_cand[q] = e[k];
                }
            }
        }
        __syncthreads();                                       // barrier 2
        const int cnt = s_cnt[p];

        float tau;
        if (cnt <= CAP) {
            // ---- exact Newton/Michelot, run redundantly by EVERY warp ----
            float t0 = thresh;
#pragma unroll 1
            for (int it = 0; it < 64; ++it) {
                float s = 0.0f, k = 0.0f;
                for (int i = lane; i < cnt; i += 32) {
                    float c = s_cand[i];
                    if (c > t0) { s += c; k += 1.0f; }
                }
#pragma unroll
                for (int o = 16; o > 0; o >>= 1) {
                    s += __shfl_xor_sync(0xffffffffu, s, o);
                    k += __shfl_xor_sync(0xffffffffu, k, o);
                }
                if (k < 0.5f) break;          // safety (cannot happen in theory)
                float nt = (s - 1.0f) / k;
                if (nt == t0) break;          // exact fixed point
                t0 = nt;
            }
            tau = t0;
        } else {
            // ---- fallback: block-wide Michelot over register row (uniform
            //      branch, internally barriered; never expected) ----
            float t0 = thresh;
#pragma unroll 1
            for (int it = 0; it < 64; ++it) {
                float s = 0.0f, k = 0.0f;
#pragma unroll
                for (int i = 0; i < 4; ++i) {
                    const float e[4] = {v[i].x, v[i].y, v[i].z, v[i].w};
#pragma unroll
                    for (int q = 0; q < 4; ++q)
                        if (e[q] > t0) { s += e[q]; k += 1.0f; }
                }
#pragma unroll
                for (int o = 16; o > 0; o >>= 1) {
                    s += __shfl_xor_sync(0xffffffffu, s, o);
                    k += __shfl_xor_sync(0xffffffffu, k, o);
                }
                const int wid = tid >> 5;
                if (lane == 0) { s_red[2 * wid] = s; s_red[2 * wid + 1] = k; }
                __syncthreads();
                if (tid == 0) {
                    float Sx = 0.0f, K = 0.0f;
                    for (int w2 = 0; w2 < 16; ++w2) { Sx += s_red[2 * w2]; K += s_red[2 * w2 + 1]; }
                    float nt = (K < 0.5f) ? t0 : (Sx - 1.0f) / K;
                    s_done = (nt == t0) || (K < 0.5f);
                    s_tau  = nt;
                }
                __syncthreads();
                t0 = s_tau;
                if (s_done) break;
            }
            tau = t0;
        }

        // ---- emit output from registers (streaming stores) ----
        float4* __restrict__ y4 = reinterpret_cast<float4*>(out + j * COLS);
#pragma unroll
        for (int i = 0; i < 4; ++i) {
            float4 rr;
            rr.x = fmaxf(v[i].x - tau, 0.0f);
            rr.y = fmaxf(v[i].y - tau, 0.0f);
            rr.z = fmaxf(v[i].z - tau, 0.0f);
            rr.w = fmaxf(v[i].w - tau, 0.0f);
            __stcs(y4 + tid + i * THREADS, rr);
        }
        p ^= 1;
    }
}

extern "C" void kernel_launch(void* const* d_in, const int* in_sizes, int n_in,
                              void* d_out, int out_size)
{
    const float* x = (const float*)d_in[0];
    float* out     = (float*)d_out;
    const int rows = in_sizes[0] / COLS;
    sparsemax_l2pf<<<GRID, THREADS>>>(x, out, rows);
}

// round 6
// speedup vs baseline: 1.3648x; 1.0907x over previous
#include <cuda_runtime.h>
#include <cstdint>
#include <float.h>

// Sparsemax as two pure streaming kernels.
//
// K1: one block per row. Pass A: stream row from DRAM, compute max.
//     Pass B: re-read row (L2 hit, it was just streamed), gather the
//     candidates > max-1 (support of sparsemax is contained there; ~6 for
//     Gaussian rows), exact Newton/Michelot solve on them, write tau[row].
// K2: elementwise out = max(x - tau[row], 0). x (~128MB) is ~L2-sized and
//     was just streamed by K1; process rows in reverse (freshest first) and
//     use evict-first stores so output traffic doesn't evict x from L2.

#define COLS     8192
#define C4       (COLS / 4)
#define T1       256
#define VPT1     (C4 / T1)      // 8 float4 per thread
#define CAP      256
#define MAXROWS  8192

__device__ float g_tau[MAXROWS];

// ---------------- K1: per-row tau ----------------
__global__ __launch_bounds__(T1)
void sparsemax_tau(const float* __restrict__ x, int rows)
{
    __shared__ float s_red[T1 / 32];
    __shared__ float s_cand[CAP];
    __shared__ int   s_cnt;
    __shared__ float s_max;
    __shared__ float s_tau;
    __shared__ int   s_done;
    __shared__ float s_fb[2 * (T1 / 32)];

    const int tid  = threadIdx.x;
    const int lane = tid & 31;
    const int wid  = tid >> 5;
    const long long row = blockIdx.x;
    if (row >= rows) return;

    const float4* __restrict__ xr = reinterpret_cast<const float4*>(x + row * COLS);

    if (tid == 0) s_cnt = 0;

    // ---- pass A: row max (DRAM stream, MLP=8) ----
    float m = -FLT_MAX;
#pragma unroll
    for (int i = 0; i < VPT1; ++i) {
        float4 v = xr[tid + i * T1];
        m = fmaxf(m, fmaxf(fmaxf(v.x, v.y), fmaxf(v.z, v.w)));
    }
#pragma unroll
    for (int o = 16; o > 0; o >>= 1) m = fmaxf(m, __shfl_xor_sync(0xffffffffu, m, o));
    if (lane == 0) s_red[wid] = m;
    __syncthreads();
    if (wid == 0) {
        float t = (lane < T1 / 32) ? s_red[lane] : -FLT_MAX;
#pragma unroll
        for (int o = 4; o > 0; o >>= 1) t = fmaxf(t, __shfl_xor_sync(0xffffffffu, t, o));
        if (lane == 0) s_max = t;
    }
    __syncthreads();
    const float thresh = s_max - 1.0f;      // tau >= thresh always

    // ---- pass B: gather candidates > thresh (row is L2-resident) ----
#pragma unroll
    for (int i = 0; i < VPT1; ++i) {
        float4 v = xr[tid + i * T1];
        const float e[4] = {v.x, v.y, v.z, v.w};
#pragma unroll
        for (int k = 0; k < 4; ++k) {
            if (e[k] > thresh) {
                int q = atomicAdd(&s_cnt, 1);
                if (q < CAP) s_cand[q] = e[k];
            }
        }
    }
    __syncthreads();
    const int cnt = s_cnt;

    if (cnt <= CAP) {
        // ---- exact Newton/Michelot on the tiny candidate set (warp 0) ----
        if (wid == 0) {
            float t0 = thresh;
#pragma unroll 1
            for (int it = 0; it < 64; ++it) {
                float s = 0.0f, k = 0.0f;
                for (int i = lane; i < cnt; i += 32) {
                    float c = s_cand[i];
                    if (c > t0) { s += c; k += 1.0f; }
                }
#pragma unroll
                for (int o = 16; o > 0; o >>= 1) {
                    s += __shfl_xor_sync(0xffffffffu, s, o);
                    k += __shfl_xor_sync(0xffffffffu, k, o);
                }
                if (k < 0.5f) break;          // safety (cannot happen in theory)
                float nt = (s - 1.0f) / k;
                if (nt == t0) break;          // exact fixed point
                t0 = nt;
            }
            if (lane == 0) g_tau[row] = t0;
        }
    } else {
        // ---- fallback: block Michelot over the row (L2-resident) ----
        float t0 = thresh;
#pragma unroll 1
        for (int it = 0; it < 64; ++it) {
            float s = 0.0f, k = 0.0f;
#pragma unroll
            for (int i = 0; i < VPT1; ++i) {
                float4 v = xr[tid + i * T1];
                const float e[4] = {v.x, v.y, v.z, v.w};
#pragma unroll
                for (int q = 0; q < 4; ++q)
                    if (e[q] > t0) { s += e[q]; k += 1.0f; }
            }
#pragma unroll
            for (int o = 16; o > 0; o >>= 1) {
                s += __shfl_xor_sync(0xffffffffu, s, o);
                k += __shfl_xor_sync(0xffffffffu, k, o);
            }
            if (lane == 0) { s_fb[2 * wid] = s; s_fb[2 * wid + 1] = k; }
            __syncthreads();
            if (tid == 0) {
                float Sx = 0.0f, K = 0.0f;
                for (int w = 0; w < T1 / 32; ++w) { Sx += s_fb[2 * w]; K += s_fb[2 * w + 1]; }
                float nt = (K < 0.5f) ? t0 : (Sx - 1.0f) / K;
                s_done = (nt == t0) || (K < 0.5f);
                s_tau  = nt;
            }
            __syncthreads();
            t0 = s_tau;
            if (s_done) break;
        }
        if (tid == 0) g_tau[row] = t0;
    }
}

// ---------------- K2: elementwise apply ----------------
#define T2 256
__global__ __launch_bounds__(T2)
void sparsemax_apply(const float* __restrict__ x, float* __restrict__ out, int rows)
{
    // reverse row order: rows K1 touched last are freshest in L2
    const long long row = (long long)(rows - 1) - blockIdx.x;
    if (row < 0) return;

    const float tau = g_tau[row];
    const float4* __restrict__ xr = reinterpret_cast<const float4*>(x + row * COLS);
    float4* __restrict__ yr       = reinterpret_cast<float4*>(out + row * COLS);

#pragma unroll
    for (int i = 0; i < C4 / T2; ++i) {
        float4 v = xr[threadIdx.x + i * T2];
        float4 r;
        r.x = fmaxf(v.x - tau, 0.0f);
        r.y = fmaxf(v.y - tau, 0.0f);
        r.z = fmaxf(v.z - tau, 0.0f);
        r.w = fmaxf(v.w - tau, 0.0f);
        __stcs(yr + threadIdx.x + i * T2, r);   // evict-first: keep x in L2
    }
}

extern "C" void kernel_launch(void* const* d_in, const int* in_sizes, int n_in,
                              void* d_out, int out_size)
{
    const float* x = (const float*)d_in[0];
    float* out     = (float*)d_out;
    const int rows = in_sizes[0] / COLS;
    sparsemax_tau<<<rows, T1>>>(x, rows);
    sparsemax_apply<<<rows, T2>>>(x, out, rows);
}